// round 13
// baseline (speedup 1.0000x reference)
#include <cuda_runtime.h>
#include <math.h>

// Problem dims (fixed by setup_inputs)
#define NB   8
#define NG   1024
#define NK   32
#define NC   168
#define NFD  56
#define NCH  336
#define GKS  (NG * NK)     // 32768
#define NBG  (NB * NG)     // 8192

// Persistent grid: 6 blocks/SM * 148 SMs -> all blocks resident (spin-safe)
#define GRID_F 888

__device__ double                g_part[GRID_F][4];
__device__ unsigned int          g_cnt_z = 0;
__device__ unsigned int          g_cnt_x = 0;
__device__ volatile unsigned int g_done_z = 0;
__device__ volatile unsigned int g_done_x = 0;
__device__ float                 g_inv[2];   // [0]=1/(std_x+eps), [1]=1/(std_xyz+eps)

// ---------------------------------------------------------------------------
// Precise fast sincos: Cody-Waite reduction by 2*pi, then MUFU sin/cos.
// ---------------------------------------------------------------------------
namespace cw {
constexpr double TWO_PI_D = 6.283185307179586476925286766559;
constexpr float  RED_A = 6.28125f;                                       // exact
constexpr float  RED_B = (float)(TWO_PI_D - (double)RED_A);
constexpr float  RED_C = (float)(TWO_PI_D - (double)RED_A - (double)RED_B);
constexpr float  INV_2PI = 0.15915494309189535f;
}

__device__ __forceinline__ void fsincos(float x, float& s, float& c) {
    float n = rintf(x * cw::INV_2PI);
    float y = fmaf(n, -cw::RED_A, x);
    y = fmaf(n, -cw::RED_B, y);
    y = fmaf(n, -cw::RED_C, y);
    s = __sinf(y);
    c = __cosf(y);
}

// log2(1000)/56
constexpr float K_LOG2A_FD = 0.17796043365468013f;

__device__ __forceinline__ void warp_reduce2(double& a, double& b) {
    #pragma unroll
    for (int o = 16; o; o >>= 1) {
        a += __shfl_down_sync(0xffffffffu, a, o);
        b += __shfl_down_sync(0xffffffffu, b, o);
    }
}

// ---------------------------------------------------------------------------
// smem layout (floats):
//   s_w   [32][177] : normalized knn_x k-major (phase B only)
//   s_xn  [3][32]   : normalized knn_xyz [d][k]
//   s_emb [7][33]   : geometric embedding, padded stride 33 (phase A only)
//   s_lct [336]     : lc-side trig per channel
//   s_inv [56]      : 1/alpha^(f/56)
// ---------------------------------------------------------------------------
#define SW_STRIDE 177
#define S_W     0
#define S_XN    (S_W + NK * SW_STRIDE)       // 5664
#define S_EMB   (S_XN + 3 * NK)              // 5760
#define S_LCT   (S_EMB + 7 * 33)             // 5991
#define S_INV   (S_LCT + NCH)                // 6327
#define SMEM_FLOATS (S_INV + NFD)            // 6383 (~25 KB)

__global__ __launch_bounds__(256, 6)
void k_fused(const float* __restrict__ lc_xyz, const float* __restrict__ lc_x,
             const float* __restrict__ knn_xyz, const float* __restrict__ knn_x,
             float* __restrict__ out) {
    __shared__ float sm[SMEM_FLOATS];
    __shared__ double sh[8][4];
    __shared__ unsigned int s_ez, s_ex;
    __shared__ int s_last;

    const int t = threadIdx.x;

    if (t == 0) { s_ez = g_done_z; s_ex = g_done_x; }
    if (t < NFD)
        sm[S_INV + t] = 1.0f / exp2f((float)t * K_LOG2A_FD);
    __syncthreads();

    // ===================== PHASE Z: knn_xyz std (3 MB) ======================
    {
        float sz = 0.0f, sz2 = 0.0f;
        for (int tile = blockIdx.x; tile < NBG; tile += GRID_F) {
            if (t < 96) {
                float v = knn_xyz[tile * 96 + t]
                        - __ldg(lc_xyz + tile * 3 + t % 3);
                sz += v; sz2 += v * v;
            }
        }
        double a = sz, b = sz2;
        warp_reduce2(a, b);
        int w = t >> 5;
        if ((t & 31) == 0) { sh[w][0] = a; sh[w][1] = b; }
        __syncthreads();
        if (t == 0) {
            double r0 = 0, r1 = 0;
            #pragma unroll
            for (int i = 0; i < 8; i++) { r0 += sh[i][0]; r1 += sh[i][1]; }
            g_part[blockIdx.x][0] = r0; g_part[blockIdx.x][1] = r1;
            __threadfence();
            s_last = (atomicAdd(&g_cnt_z, 1u) == GRID_F - 1) ? 1 : 0;
        }
        __syncthreads();
        if (s_last) {
            double a2 = 0, b2 = 0;
            for (int i = t; i < GRID_F; i += 256) {
                a2 += g_part[i][0]; b2 += g_part[i][1];
            }
            warp_reduce2(a2, b2);
            if ((t & 31) == 0) { sh[w][0] = a2; sh[w][1] = b2; }
            __syncthreads();
            if (t == 0) {
                double r0 = 0, r1 = 0;
                #pragma unroll
                for (int i = 0; i < 8; i++) { r0 += sh[i][0]; r1 += sh[i][1]; }
                const double nz = (double)NBG * NK * 3;
                double vz = (r1 - r0 * r0 / nz) / (nz - 1.0);
                ((volatile float*)g_inv)[1] = (float)(1.0 / (sqrt(vz) + 1e-5));
                g_cnt_z = 0;
                __threadfence();
                g_done_z = s_ez + 1;
            }
        }
        if (t == 0) { while (g_done_z == s_ez) __nanosleep(32); }
        __syncthreads();
    }
    const float inv_z = ((volatile float*)g_inv)[1];

    // ========= PHASE A: reduce knn_x + write channels 168..335 ==============
    float sx = 0.0f, sx2 = 0.0f;
    for (int tile = blockIdx.x; tile < NBG; tile += GRID_F) {
        const int bg = tile;
        if (t < 96) {                         // normalized knn_xyz [d][k]
            int d = t % 3, k = t / 3;
            float v = knn_xyz[bg * 96 + t] - __ldg(lc_xyz + bg * 3 + d);
            sm[S_XN + d * NK + k] = v * inv_z;
        }
        if (t < 3 * NFD) {                    // lc-side trig (raw lc_xyz)
            int d = t / NFD, f = t % NFD;
            float inv = 1.0f / exp2f((float)f * K_LOG2A_FD);
            float a = 100.0f * __ldg(lc_xyz + bg * 3 + d) * inv;
            float sn, cs;
            fsincos(a, sn, cs);
            sm[S_LCT + d * 112 + f]      = sn;
            sm[S_LCT + d * 112 + 56 + f] = cs;
        }
        {   // reduce knn_x tile (registers only)
            const float4* kx4 = (const float4*)(knn_x + (size_t)bg * NK * NC);
            const float4* lx4 = (const float4*)(lc_x + (size_t)bg * NC);
            #pragma unroll
            for (int it = 0; it < 6; ++it) {
                int i = t + it * 256;
                if (i < 1344) {
                    float4 v = kx4[i];
                    float4 l = __ldg(&lx4[i % 42]);
                    float d0 = v.x - l.x, d1 = v.y - l.y;
                    float d2 = v.z - l.z, d3 = v.w - l.w;
                    sx  += (d0 + d1) + (d2 + d3);
                    sx2 += (d0 * d0 + d1 * d1) + (d2 * d2 + d3 * d3);
                }
            }
        }
        __syncthreads();
        if (t < NK) {                         // 7-ch embedding, stride 33
            int k = t;
            float a0 = sm[S_XN + k], a1 = sm[S_XN + NK + k];
            float a2 = sm[S_XN + 2 * NK + k];
            float b0 = __ldg(lc_xyz + bg * 3 + 0);
            float b1 = __ldg(lc_xyz + bg * 3 + 1);
            float b2 = __ldg(lc_xyz + bg * 3 + 2);
            sm[S_EMB + 0 * 33 + k] = a0;
            sm[S_EMB + 1 * 33 + k] = a1;
            sm[S_EMB + 2 * 33 + k] = a2;
            sm[S_EMB + 3 * 33 + k] = a1 * b2 - a2 * b1;
            sm[S_EMB + 4 * 33 + k] = a2 * b0 - a0 * b2;
            sm[S_EMB + 5 * 33 + k] = a0 * b1 - a1 * b0;
            sm[S_EMB + 6 * 33 + k] = a0 * b0 + a1 * b1 + a2 * b2;
        }
        __syncthreads();

        // trig + store, channels >= 168: tasks (d in {1,2}, f, kq)
        const int b = bg >> 10;
        const int g = bg & (NG - 1);
        float* obase = out + (size_t)b * NCH * GKS + (size_t)g * NK;
        const int kq = t & 7, k0 = kq * 4, r0 = t >> 3;
        #pragma unroll
        for (int it = 0; it < 4; ++it) {
            int r = r0 + it * 32;
            if (r < 112) {
                int dd = r / 56;              // 0 -> d=1, 1 -> d=2
                int f  = r - dd * 56;
                int d  = dd + 1;
                float amp = 100.0f * sm[S_INV + f];
                const float4 x = *(const float4*)&sm[S_XN + d * NK + k0];
                float s0, c0, s1, c1, s2, c2, s3, c3;
                fsincos(amp * x.x, s0, c0);
                fsincos(amp * x.y, s1, c1);
                fsincos(amp * x.z, s2, c2);
                fsincos(amp * x.w, s3, c3);
                const float* erow = &sm[S_EMB + (f % 7) * 33 + k0];
                float w0 = erow[0], w1 = erow[1], w2 = erow[2], w3 = erow[3];
                int cb2 = d * 112 + 56 + f;   // cos channel (>=168 always)
                float l2 = sm[S_LCT + cb2];
                float4 r2; float p;
                p = c0 + l2; r2.x = (w0 + p) * p;
                p = c1 + l2; r2.y = (w1 + p) * p;
                p = c2 + l2; r2.z = (w2 + p) * p;
                p = c3 + l2; r2.w = (w3 + p) * p;
                __stcs((float4*)(obase + (size_t)cb2 * GKS + k0), r2);
                if (d == 2) {                 // sin channel 224+f also >=168
                    int cb1 = 224 + f;
                    float l1 = sm[S_LCT + cb1];
                    float4 r1;
                    p = s0 + l1; r1.x = (w0 + p) * p;
                    p = s1 + l1; r1.y = (w1 + p) * p;
                    p = s2 + l1; r1.z = (w2 + p) * p;
                    p = s3 + l1; r1.w = (w3 + p) * p;
                    __stcs((float4*)(obase + (size_t)cb1 * GKS + k0), r1);
                }
            }
        }
        __syncthreads();
    }

    // ---- publish inv_x -----------------------------------------------------
    {
        double a = sx, b = sx2;
        warp_reduce2(a, b);
        int w = t >> 5;
        if ((t & 31) == 0) { sh[w][0] = a; sh[w][1] = b; }
        __syncthreads();
        if (t == 0) {
            double r0 = 0, r1 = 0;
            #pragma unroll
            for (int i = 0; i < 8; i++) { r0 += sh[i][0]; r1 += sh[i][1]; }
            g_part[blockIdx.x][2] = r0; g_part[blockIdx.x][3] = r1;
            __threadfence();
            s_last = (atomicAdd(&g_cnt_x, 1u) == GRID_F - 1) ? 1 : 0;
        }
        __syncthreads();
        if (s_last) {
            double a2 = 0, b2 = 0;
            for (int i = t; i < GRID_F; i += 256) {
                a2 += g_part[i][2]; b2 += g_part[i][3];
            }
            warp_reduce2(a2, b2);
            if ((t & 31) == 0) { sh[w][0] = a2; sh[w][1] = b2; }
            __syncthreads();
            if (t == 0) {
                double r0 = 0, r1 = 0;
                #pragma unroll
                for (int i = 0; i < 8; i++) { r0 += sh[i][0]; r1 += sh[i][1]; }
                const double nx = (double)NBG * NK * NC;
                double vx = (r1 - r0 * r0 / nx) / (nx - 1.0);
                ((volatile float*)g_inv)[0] = (float)(1.0 / (sqrt(vx) + 1e-5));
                g_cnt_x = 0;
                __threadfence();
                g_done_x = s_ex + 1;
            }
        }
        if (t == 0) { while (g_done_x == s_ex) __nanosleep(32); }
        __syncthreads();
    }
    const float inv_x = ((volatile float*)g_inv)[0];

    // ========= PHASE B: write channels 0..167 ===============================
    for (int tile = blockIdx.x; tile < NBG; tile += GRID_F) {
        const int bg = tile;
        if (t < 96) {
            int d = t % 3, k = t / 3;
            float v = knn_xyz[bg * 96 + t] - __ldg(lc_xyz + bg * 3 + d);
            sm[S_XN + d * NK + k] = v * inv_z;
        }
        if (t < 3 * NFD) {
            int d = t / NFD, f = t % NFD;
            float inv = 1.0f / exp2f((float)f * K_LOG2A_FD);
            float a = 100.0f * __ldg(lc_xyz + bg * 3 + d) * inv;
            float sn, cs;
            fsincos(a, sn, cs);
            sm[S_LCT + d * 112 + f]      = sn;
            sm[S_LCT + d * 112 + 56 + f] = cs;
        }
        {   // normalized knn_x -> s_w[k][c], stride 177
            const float4* kx4 = (const float4*)(knn_x + (size_t)bg * NK * NC);
            const float4* lx4 = (const float4*)(lc_x + (size_t)bg * NC);
            #pragma unroll
            for (int it = 0; it < 6; ++it) {
                int i = t + it * 256;
                if (i < 1344) {
                    int k  = i / 42;
                    int c4 = i - k * 42;
                    float4 v = kx4[i];
                    float4 l = __ldg(&lx4[c4]);
                    float* dst = &sm[S_W + k * SW_STRIDE + c4 * 4];
                    dst[0] = (v.x - l.x) * inv_x;
                    dst[1] = (v.y - l.y) * inv_x;
                    dst[2] = (v.z - l.z) * inv_x;
                    dst[3] = (v.w - l.w) * inv_x;
                }
            }
        }
        __syncthreads();

        // trig + store, channels < 168: tasks (d in {0,1}, f, kq)
        const int b = bg >> 10;
        const int g = bg & (NG - 1);
        float* obase = out + (size_t)b * NCH * GKS + (size_t)g * NK;
        const int kq = t & 7, k0 = kq * 4, r0 = t >> 3;
        const int wb = S_W + k0 * SW_STRIDE;
        #pragma unroll
        for (int it = 0; it < 4; ++it) {
            int r = r0 + it * 32;
            if (r < 112) {
                int d = r / 56;               // 0 or 1
                int f = r - d * 56;
                float amp = 100.0f * sm[S_INV + f];
                const float4 x = *(const float4*)&sm[S_XN + d * NK + k0];
                float s0, c0, s1, c1, s2, c2, s3, c3;
                fsincos(amp * x.x, s0, c0);
                fsincos(amp * x.y, s1, c1);
                fsincos(amp * x.z, s2, c2);
                fsincos(amp * x.w, s3, c3);
                int cb1 = d * 112 + f;        // sin channel (<168 always)
                float l1 = sm[S_LCT + cb1];
                float4 r1; float p;
                p = s0 + l1; r1.x = (sm[wb + 0 * SW_STRIDE + cb1] + p) * p;
                p = s1 + l1; r1.y = (sm[wb + 1 * SW_STRIDE + cb1] + p) * p;
                p = s2 + l1; r1.z = (sm[wb + 2 * SW_STRIDE + cb1] + p) * p;
                p = s3 + l1; r1.w = (sm[wb + 3 * SW_STRIDE + cb1] + p) * p;
                __stcs((float4*)(obase + (size_t)cb1 * GKS + k0), r1);
                if (d == 0) {                 // cos channel 56+f also <168
                    int cb2 = 56 + f;
                    float l2 = sm[S_LCT + cb2];
                    float4 r2;
                    p = c0 + l2; r2.x = (sm[wb + 0 * SW_STRIDE + cb2] + p) * p;
                    p = c1 + l2; r2.y = (sm[wb + 1 * SW_STRIDE + cb2] + p) * p;
                    p = c2 + l2; r2.z = (sm[wb + 2 * SW_STRIDE + cb2] + p) * p;
                    p = c3 + l2; r2.w = (sm[wb + 3 * SW_STRIDE + cb2] + p) * p;
                    __stcs((float4*)(obase + (size_t)cb2 * GKS + k0), r2);
                }
            }
        }
        __syncthreads();
    }
}

// ---------------------------------------------------------------------------
extern "C" void kernel_launch(void* const* d_in, const int* in_sizes, int n_in,
                              void* d_out, int out_size) {
    const float* lc_xyz  = (const float*)d_in[0];
    const float* lc_x    = (const float*)d_in[1];
    const float* knn_xyz = (const float*)d_in[2];
    const float* knn_x   = (const float*)d_in[3];
    float* out = (float*)d_out;

    k_fused<<<GRID_F, 256>>>(lc_xyz, lc_x, knn_xyz, knn_x, out);
}